// round 7
// baseline (speedup 1.0000x reference)
#include <cuda_runtime.h>
#include <cuda_fp16.h>
#include <stdint.h>

#define NMAX 100000
#define EMAX 1600000

// ---------------- scratch (static device globals) ----------------
__device__ __align__(16) float  g_q  [(size_t)NMAX * 128];
__device__ __align__(16) __half g_kv [(size_t)2 * NMAX * 128];   // k | v planes fp16
__device__ __align__(16) float  g_agg[(size_t)NMAX * 128];
__device__ __align__(16) float  g_h  [(size_t)NMAX * 128];
__device__ __align__(16) float  g_hn [(size_t)NMAX * 128];
__device__ __align__(16) float  g_t2 [(size_t)NMAX * 64];
// CSR
__device__ int    g_deg[NMAX];
__device__ int    g_rowptr[NMAX + 1];
__device__ int    g_cursor[NMAX];
__device__ int    g_esrc[EMAX];
__device__ __align__(8) float2 g_eea[EMAX];

__device__ __forceinline__ int clampi(int v, int hi) {
    return v < 0 ? 0 : (v >= hi ? hi - 1 : v);
}
__device__ __forceinline__ uint32_t f2tf32(float f) {
    uint32_t u;
    asm("cvt.rna.tf32.f32 %0, %1;" : "=r"(u) : "f"(f));
    return u;
}
__device__ __forceinline__ void mma_tf32(float4& c, const uint32_t a[4], const uint32_t b[2]) {
    asm("mma.sync.aligned.m16n8k8.row.col.f32.tf32.tf32.f32 "
        "{%0,%1,%2,%3}, {%4,%5,%6,%7}, {%8,%9}, {%0,%1,%2,%3};"
        : "+f"(c.x), "+f"(c.y), "+f"(c.z), "+f"(c.w)
        : "r"(a[0]), "r"(a[1]), "r"(a[2]), "r"(a[3]), "r"(b[0]), "r"(b[1]));
}

// ---------------- CSR build ----------------
__global__ void zero_deg(int n) {
    int i = blockIdx.x * blockDim.x + threadIdx.x;
    if (i < n) g_deg[i] = 0;
}
// 4 edges per thread, batched
__global__ void hist_kernel(const int* __restrict__ ei, int E, int n) {
    int base = (blockIdx.x * blockDim.x + threadIdx.x) * 4;
    if (base >= E) return;
    int d[4];
#pragma unroll
    for (int u = 0; u < 4; ++u) {
        int e = min(base + u, E - 1);
        d[u] = clampi(__ldg(ei + E + e), n);
    }
#pragma unroll
    for (int u = 0; u < 4; ++u)
        if (base + u < E) atomicAdd(&g_deg[d[u]], 1);
}
__global__ __launch_bounds__(1024)
void scan_kernel(int n) {
    __shared__ int sh[1024];
    int t = threadIdx.x;
    int chunk = (n + 1023) >> 10;
    int b = t * chunk;
    int e = min(n, b + chunk);
    int s = 0;
    for (int i = b; i < e; ++i) s += g_deg[i];
    sh[t] = s;
    __syncthreads();
    for (int off = 1; off < 1024; off <<= 1) {
        int v = (t >= off) ? sh[t - off] : 0;
        __syncthreads();
        sh[t] += v;
        __syncthreads();
    }
    int base = (t == 0) ? 0 : sh[t - 1];
    for (int i = b; i < e; ++i) {
        int d = g_deg[i];
        g_rowptr[i] = base;
        g_cursor[i] = base;
        base += d;
    }
    if (t == 1023) g_rowptr[n] = sh[1023];
}
// 4 edges per thread, batched loads + batched atomics
__global__ void scatter_kernel(const int* __restrict__ ei, const float* __restrict__ ea,
                               int E, int n) {
    int base = (blockIdx.x * blockDim.x + threadIdx.x) * 4;
    if (base >= E) return;
    int srcs[4], dsts[4];
    float2 eav[4];
#pragma unroll
    for (int u = 0; u < 4; ++u) {
        int e = min(base + u, E - 1);
        srcs[u] = clampi(__ldg(ei + e), n);
        dsts[u] = clampi(__ldg(ei + E + e), n);
        eav[u]  = *reinterpret_cast<const float2*>(ea + (size_t)e * 2);
    }
    int pos[4];
#pragma unroll
    for (int u = 0; u < 4; ++u)
        if (base + u < E) pos[u] = atomicAdd(&g_cursor[dsts[u]], 1);
#pragma unroll
    for (int u = 0; u < 4; ++u)
        if (base + u < E) {
            g_esrc[pos[u]] = srcs[u];
            g_eea[pos[u]]  = eav[u];
        }
}

// ---------------- tf32 tensor-core GEMM, K=128, M-tile=128, N-tile=NT ----------------
template<int NT, int EPI>
__global__ __launch_bounds__(256)
void gemm_tf32(const float* __restrict__ A, const float* __restrict__ B,
               const float* __restrict__ bias, const float* __restrict__ resid,
               float* __restrict__ C, __half* __restrict__ Hkv, int M, int NCOLS)
{
    constexpr int WM = (NT == 128) ? 2 : 4;
    constexpr int WN = 8 / WM;
    constexpr int MFRAG = 8 / WM;
    constexpr int NFRAG = NT / (WN * 8);

    __shared__ uint32_t As[128][20];
    __shared__ uint32_t Bs[16][NT + 8];

    const int t = threadIdx.x;
    const int lane = t & 31;
    const int wid  = t >> 5;
    const int warp_m = wid / WN;
    const int warp_n = wid % WN;
    const int m0 = blockIdx.x * 128;
    const int n0 = blockIdx.y * NT;
    const int lr = lane >> 2, lc = lane & 3;

    float4 acc[MFRAG][NFRAG];
#pragma unroll
    for (int i = 0; i < MFRAG; ++i)
#pragma unroll
        for (int j = 0; j < NFRAG; ++j) acc[i][j] = make_float4(0.f, 0.f, 0.f, 0.f);

    const int arow = t >> 1;
    const int acb  = (t & 1) * 8;
    int agr = m0 + arow; if (agr >= M) agr = M - 1;
    const float* Ap = A + (size_t)agr * 128 + acb;

    const int brow = t >> 4;
    const int bcb  = (t & 15) * (NT / 16);
    const float* Bp = B + (size_t)brow * NCOLS + n0 + bcb;

    for (int k0 = 0; k0 < 128; k0 += 16) {
        float4 av0 = *reinterpret_cast<const float4*>(Ap + k0);
        float4 av1 = *reinterpret_cast<const float4*>(Ap + k0 + 4);
        As[arow][acb + 0] = f2tf32(av0.x); As[arow][acb + 1] = f2tf32(av0.y);
        As[arow][acb + 2] = f2tf32(av0.z); As[arow][acb + 3] = f2tf32(av0.w);
        As[arow][acb + 4] = f2tf32(av1.x); As[arow][acb + 5] = f2tf32(av1.y);
        As[arow][acb + 6] = f2tf32(av1.z); As[arow][acb + 7] = f2tf32(av1.w);
#pragma unroll
        for (int j = 0; j < NT / 64; ++j) {
            float4 bv = *reinterpret_cast<const float4*>(Bp + (size_t)k0 * NCOLS + j * 4);
            Bs[brow][bcb + j * 4 + 0] = f2tf32(bv.x);
            Bs[brow][bcb + j * 4 + 1] = f2tf32(bv.y);
            Bs[brow][bcb + j * 4 + 2] = f2tf32(bv.z);
            Bs[brow][bcb + j * 4 + 3] = f2tf32(bv.w);
        }
        __syncthreads();

#pragma unroll
        for (int ks = 0; ks < 16; ks += 8) {
            uint32_t afr[MFRAG][4];
#pragma unroll
            for (int fm = 0; fm < MFRAG; ++fm) {
                int mr = warp_m * (MFRAG * 16) + fm * 16 + lr;
                afr[fm][0] = As[mr][ks + lc];
                afr[fm][1] = As[mr + 8][ks + lc];
                afr[fm][2] = As[mr][ks + lc + 4];
                afr[fm][3] = As[mr + 8][ks + lc + 4];
            }
            uint32_t bfr[NFRAG][2];
#pragma unroll
            for (int fn = 0; fn < NFRAG; ++fn) {
                int nc = warp_n * (NFRAG * 8) + fn * 8 + lr;
                bfr[fn][0] = Bs[ks + lc][nc];
                bfr[fn][1] = Bs[ks + lc + 4][nc];
            }
#pragma unroll
            for (int fm = 0; fm < MFRAG; ++fm)
#pragma unroll
                for (int fn = 0; fn < NFRAG; ++fn)
                    mma_tf32(acc[fm][fn], afr[fm], bfr[fn]);
        }
        __syncthreads();
    }

    const int plane = n0 >> 7;
#pragma unroll
    for (int fm = 0; fm < MFRAG; ++fm) {
        int r0 = m0 + warp_m * (MFRAG * 16) + fm * 16 + lr;
        int r1 = r0 + 8;
#pragma unroll
        for (int fn = 0; fn < NFRAG; ++fn) {
            int cl = warp_n * (NFRAG * 8) + fn * 8 + 2 * lc;
            float4 c = acc[fm][fn];
            if (EPI == 0) {
                if (plane == 0) {
                    if (r0 < M) *reinterpret_cast<float2*>(C + (size_t)r0 * 128 + cl) = make_float2(c.x, c.y);
                    if (r1 < M) *reinterpret_cast<float2*>(C + (size_t)r1 * 128 + cl) = make_float2(c.z, c.w);
                } else {
                    __half* hp = Hkv + (size_t)(plane - 1) * M * 128;
                    if (r0 < M) *reinterpret_cast<__half2*>(hp + (size_t)r0 * 128 + cl) = __floats2half2_rn(c.x, c.y);
                    if (r1 < M) *reinterpret_cast<__half2*>(hp + (size_t)r1 * 128 + cl) = __floats2half2_rn(c.z, c.w);
                }
            } else {
                int col = n0 + cl;
                float b0 = bias[col], b1 = bias[col + 1];
                if (EPI == 1) {
                    if (r0 < M) {
                        float2 rr = *reinterpret_cast<const float2*>(resid + (size_t)r0 * NCOLS + col);
                        *reinterpret_cast<float2*>(C + (size_t)r0 * NCOLS + col) =
                            make_float2(c.x + b0 + rr.x, c.y + b1 + rr.y);
                    }
                    if (r1 < M) {
                        float2 rr = *reinterpret_cast<const float2*>(resid + (size_t)r1 * NCOLS + col);
                        *reinterpret_cast<float2*>(C + (size_t)r1 * NCOLS + col) =
                            make_float2(c.z + b0 + rr.x, c.w + b1 + rr.y);
                    }
                } else {
                    if (r0 < M)
                        *reinterpret_cast<float2*>(C + (size_t)r0 * NCOLS + col) =
                            make_float2(fmaxf(c.x + b0, 0.f), fmaxf(c.y + b1, 0.f));
                    if (r1 < M)
                        *reinterpret_cast<float2*>(C + (size_t)r1 * NCOLS + col) =
                            make_float2(fmaxf(c.z + b0, 0.f), fmaxf(c.w + b1, 0.f));
                }
            }
        }
    }
}

// ---------------- fused CSR attention: one warp per node, 16-edge batches ----------------
__global__ __launch_bounds__(128)
void fused_attn(const float* __restrict__ Wedge, int n)
{
    constexpr int EPW = 16;
    int i    = (blockIdx.x * blockDim.x + threadIdx.x) >> 5;
    int lane = threadIdx.x & 31;
    if (i >= n) return;
    int hg = lane >> 2;

    int beg = g_rowptr[i];
    int end = g_rowptr[i + 1];

    float4 q4 = *reinterpret_cast<const float4*>(g_q + (size_t)i * 128 + lane * 4);
    q4.x *= 0.25f; q4.y *= 0.25f; q4.z *= 0.25f; q4.w *= 0.25f;
    float w0 = Wedge[hg], w1 = Wedge[8 + hg];

    const __half* kplane = g_kv;
    const __half* vplane = g_kv + (size_t)n * 128;

    float4 accv = {0.f, 0.f, 0.f, 0.f};
    float  accd = 0.f;

    for (int j = beg; j < end; j += EPW) {
        // phase 1: CSR reads (uniform broadcast loads), fold edge bias immediately
        int   idx[EPW];
        float sb[EPW];
#pragma unroll
        for (int u = 0; u < EPW; ++u) {
            int jj = min(j + u, end - 1);
            idx[u] = __ldg(g_esrc + jj);
            float2 ea2 = g_eea[jj];
            sb[u] = ea2.x * w0 + ea2.y * w1;
        }
        // phase 2: all 2*EPW gathers in flight
        uint2 kraw[EPW];
#pragma unroll
        for (int u = 0; u < EPW; ++u)
            kraw[u] = *reinterpret_cast<const uint2*>(kplane + (size_t)idx[u] * 128 + lane * 4);
        uint2 vraw[EPW];
#pragma unroll
        for (int u = 0; u < EPW; ++u)
            vraw[u] = *reinterpret_cast<const uint2*>(vplane + (size_t)idx[u] * 128 + lane * 4);

        // phase 3: scores + exp
        float ex[EPW];
#pragma unroll
        for (int u = 0; u < EPW; ++u) {
            float2 ka = __half22float2(*reinterpret_cast<const __half2*>(&kraw[u].x));
            float2 kb = __half22float2(*reinterpret_cast<const __half2*>(&kraw[u].y));
            float p = q4.x * ka.x + q4.y * ka.y + q4.z * kb.x + q4.w * kb.y;
            p += __shfl_xor_sync(0xffffffffu, p, 1);
            p += __shfl_xor_sync(0xffffffffu, p, 2);
            float e = __expf(p + sb[u]);
            ex[u] = (j + u < end) ? e : 0.f;
            accd += ex[u];
        }
        // phase 4: weighted V accumulate
#pragma unroll
        for (int u = 0; u < EPW; ++u) {
            float2 va = __half22float2(*reinterpret_cast<const __half2*>(&vraw[u].x));
            float2 vb = __half22float2(*reinterpret_cast<const __half2*>(&vraw[u].y));
            accv.x += ex[u] * va.x;
            accv.y += ex[u] * va.y;
            accv.z += ex[u] * vb.x;
            accv.w += ex[u] * vb.y;
        }
    }

    float invd = __fdividef(1.f, accd + 1e-16f);
    float4 o = {accv.x * invd, accv.y * invd, accv.z * invd, accv.w * invd};
    *reinterpret_cast<float4*>(g_agg + (size_t)i * 128 + lane * 4) = o;
}

// ---------------- layernorm ----------------
__global__ __launch_bounds__(256)
void ln_kernel(const float* __restrict__ lw, const float* __restrict__ lb, int n)
{
    int node = (blockIdx.x * blockDim.x + threadIdx.x) >> 5;
    int lane = threadIdx.x & 31;
    if (node >= n) return;

    float4 v = *reinterpret_cast<const float4*>(g_h + (size_t)node * 128 + lane * 4);
    float s = v.x + v.y + v.z + v.w;
    float q = v.x * v.x + v.y * v.y + v.z * v.z + v.w * v.w;
#pragma unroll
    for (int o = 16; o; o >>= 1) {
        s += __shfl_xor_sync(0xffffffffu, s, o);
        q += __shfl_xor_sync(0xffffffffu, q, o);
    }
    float mu  = s * (1.f / 128.f);
    float var = q * (1.f / 128.f) - mu * mu;
    float rs  = rsqrtf(var + 1e-5f);
    float4 w4 = *reinterpret_cast<const float4*>(lw + lane * 4);
    float4 b4 = *reinterpret_cast<const float4*>(lb + lane * 4);
    float4 o;
    o.x = (v.x - mu) * rs * w4.x + b4.x;
    o.y = (v.y - mu) * rs * w4.y + b4.y;
    o.z = (v.z - mu) * rs * w4.z + b4.z;
    o.w = (v.w - mu) * rs * w4.w + b4.w;
    *reinterpret_cast<float4*>(g_hn + (size_t)node * 128 + lane * 4) = o;
}

// ---------------- final: out[N,3] = t2[N,64] @ Wc2[64,3] + bc2 ----------------
__global__ __launch_bounds__(256)
void final_kernel(const float* __restrict__ Wc2, const float* __restrict__ bc2,
                  float* __restrict__ out, int n)
{
    int node = (blockIdx.x * blockDim.x + threadIdx.x) >> 5;
    int lane = threadIdx.x & 31;
    if (node >= n) return;

    float2 tv = *reinterpret_cast<const float2*>(g_t2 + (size_t)node * 64 + lane * 2);
    int k0 = lane * 2;
    float s0 = tv.x * Wc2[k0 * 3 + 0] + tv.y * Wc2[k0 * 3 + 3];
    float s1 = tv.x * Wc2[k0 * 3 + 1] + tv.y * Wc2[k0 * 3 + 4];
    float s2 = tv.x * Wc2[k0 * 3 + 2] + tv.y * Wc2[k0 * 3 + 5];
#pragma unroll
    for (int o = 16; o; o >>= 1) {
        s0 += __shfl_xor_sync(0xffffffffu, s0, o);
        s1 += __shfl_xor_sync(0xffffffffu, s1, o);
        s2 += __shfl_xor_sync(0xffffffffu, s2, o);
    }
    if (lane == 0) {
        out[(size_t)node * 3 + 0] = s0 + bc2[0];
        out[(size_t)node * 3 + 1] = s1 + bc2[1];
        out[(size_t)node * 3 + 2] = s2 + bc2[2];
    }
}

// ---------------- launch ----------------
extern "C" void kernel_launch(void* const* d_in, const int* in_sizes, int n_in,
                              void* d_out, int out_size)
{
    const float* x     = (const float*)d_in[0];
    const int*   ei    = (const int*)d_in[1];
    const float* ea    = (const float*)d_in[2];
    const float* Wqkv  = (const float*)d_in[3];
    const float* Wedge = (const float*)d_in[4];
    const float* Wout  = (const float*)d_in[5];
    const float* bout  = (const float*)d_in[6];
    const float* lnw   = (const float*)d_in[7];
    const float* lnb   = (const float*)d_in[8];
    const float* Wc1   = (const float*)d_in[9];
    const float* bc1   = (const float*)d_in[10];
    const float* Wc2   = (const float*)d_in[11];
    const float* bc2   = (const float*)d_in[12];
    float* out = (float*)d_out;

    const int n = in_sizes[0] / 128;
    const int E = in_sizes[1] / 2;

    float *q, *agg, *h, *hn, *t2;
    __half* kv;
    cudaGetSymbolAddress((void**)&q,   g_q);
    cudaGetSymbolAddress((void**)&kv,  g_kv);
    cudaGetSymbolAddress((void**)&agg, g_agg);
    cudaGetSymbolAddress((void**)&h,   g_h);
    cudaGetSymbolAddress((void**)&hn,  g_hn);
    cudaGetSymbolAddress((void**)&t2,  g_t2);

    // CSR build
    zero_deg<<<(n + 255) / 256, 256>>>(n);
    hist_kernel<<<((E + 3) / 4 + 255) / 256, 256>>>(ei, E, n);
    scan_kernel<<<1, 1024>>>(n);
    scatter_kernel<<<((E + 3) / 4 + 255) / 256, 256>>>(ei, ea, E, n);

    // qkv = x @ Wqkv -> q fp32 + k/v fp16 planes   (tf32 tensor cores)
    gemm_tf32<128, 0><<<dim3((n + 127) / 128, 3), 256>>>(
        x, Wqkv, nullptr, nullptr, q, kv, n, 384);

    // fused per-node attention
    fused_attn<<<(n + 3) / 4, 128>>>(Wedge, n);

    // h = agg @ Wout + bout + x
    gemm_tf32<128, 1><<<dim3((n + 127) / 128, 1), 256>>>(
        agg, Wout, bout, x, h, nullptr, n, 128);

    // layernorm
    ln_kernel<<<(n + 7) / 8, 256>>>(lnw, lnb, n);

    // t2 = relu(hn @ Wc1 + bc1)
    gemm_tf32<64, 2><<<dim3((n + 127) / 128, 1), 256>>>(
        hn, Wc1, bc1, nullptr, t2, nullptr, n, 64);

    // out = t2 @ Wc2 + bc2
    final_kernel<<<(n + 7) / 8, 256>>>(Wc2, bc2, out, n);
}

// round 8
// speedup vs baseline: 1.0201x; 1.0201x over previous
#include <cuda_runtime.h>
#include <cuda_fp16.h>
#include <stdint.h>

#define NMAX 100000
#define EMAX 1600000

// ---------------- scratch (static device globals) ----------------
__device__ __align__(16) float  g_q  [(size_t)NMAX * 128];
__device__ __align__(16) __half g_kv [(size_t)2 * NMAX * 128];   // k | v planes fp16
__device__ __align__(16) float  g_agg[(size_t)NMAX * 128];
__device__ __align__(16) float  g_hn [(size_t)NMAX * 128];
__device__ __align__(16) float  g_t2 [(size_t)NMAX * 64];
// CSR
__device__ int    g_deg[NMAX];
__device__ int    g_rowptr[NMAX + 1];
__device__ int    g_cursor[NMAX];
__device__ int    g_esrc[EMAX];
__device__ __align__(8) float2 g_eea[EMAX];

__device__ __forceinline__ int clampi(int v, int hi) {
    return v < 0 ? 0 : (v >= hi ? hi - 1 : v);
}
__device__ __forceinline__ uint32_t f2tf32(float f) {
    uint32_t u;
    asm("cvt.rna.tf32.f32 %0, %1;" : "=r"(u) : "f"(f));
    return u;
}
__device__ __forceinline__ void mma_tf32(float4& c, const uint32_t a[4], const uint32_t b[2]) {
    asm("mma.sync.aligned.m16n8k8.row.col.f32.tf32.tf32.f32 "
        "{%0,%1,%2,%3}, {%4,%5,%6,%7}, {%8,%9}, {%0,%1,%2,%3};"
        : "+f"(c.x), "+f"(c.y), "+f"(c.z), "+f"(c.w)
        : "r"(a[0]), "r"(a[1]), "r"(a[2]), "r"(a[3]), "r"(b[0]), "r"(b[1]));
}

// ---------------- CSR build (simple 1-edge/thread versions) ----------------
__global__ void zero_deg(int n) {
    int i = blockIdx.x * blockDim.x + threadIdx.x;
    if (i < n) g_deg[i] = 0;
}
__global__ void hist_kernel(const int* __restrict__ ei, int E, int n) {
    int e = blockIdx.x * blockDim.x + threadIdx.x;
    if (e < E) atomicAdd(&g_deg[clampi(ei[E + e], n)], 1);
}
__global__ __launch_bounds__(1024)
void scan_kernel(int n) {
    __shared__ int sh[1024];
    int t = threadIdx.x;
    int chunk = (n + 1023) >> 10;
    int b = t * chunk;
    int e = min(n, b + chunk);
    int s = 0;
    for (int i = b; i < e; ++i) s += g_deg[i];
    sh[t] = s;
    __syncthreads();
    for (int off = 1; off < 1024; off <<= 1) {
        int v = (t >= off) ? sh[t - off] : 0;
        __syncthreads();
        sh[t] += v;
        __syncthreads();
    }
    int base = (t == 0) ? 0 : sh[t - 1];
    for (int i = b; i < e; ++i) {
        int d = g_deg[i];
        g_rowptr[i] = base;
        g_cursor[i] = base;
        base += d;
    }
    if (t == 1023) g_rowptr[n] = sh[1023];
}
__global__ void scatter_kernel(const int* __restrict__ ei, const float* __restrict__ ea,
                               int E, int n) {
    int e = blockIdx.x * blockDim.x + threadIdx.x;
    if (e >= E) return;
    int src = clampi(ei[e], n);
    int dst = clampi(ei[E + e], n);
    int pos = atomicAdd(&g_cursor[dst], 1);
    g_esrc[pos] = src;
    g_eea[pos]  = *reinterpret_cast<const float2*>(ea + (size_t)e * 2);
}

// ---------------- tf32 tensor-core GEMM, K=128, M-tile=128, N-tile=NT ----------------
// EPI 0: qkv split -> q fp32 + k/v fp16 planes
// EPI 2: bias + relu
// EPI 3: bias + resid + LayerNorm fused (NT=128 = full row), writes hn
template<int NT, int EPI>
__global__ __launch_bounds__(256)
void gemm_tf32(const float* __restrict__ A, const float* __restrict__ B,
               const float* __restrict__ bias, const float* __restrict__ resid,
               const float* __restrict__ lnw, const float* __restrict__ lnb,
               float* __restrict__ C, __half* __restrict__ Hkv, int M, int NCOLS)
{
    constexpr int WM = (NT == 128) ? 2 : 4;
    constexpr int WN = 8 / WM;
    constexpr int MFRAG = 8 / WM;
    constexpr int NFRAG = NT / (WN * 8);

    __shared__ uint32_t As[128][20];
    __shared__ uint32_t Bs[16][NT + 8];

    const int t = threadIdx.x;
    const int lane = t & 31;
    const int wid  = t >> 5;
    const int warp_m = wid / WN;
    const int warp_n = wid % WN;
    const int m0 = blockIdx.x * 128;
    const int n0 = blockIdx.y * NT;
    const int lr = lane >> 2, lc = lane & 3;

    float4 acc[MFRAG][NFRAG];
#pragma unroll
    for (int i = 0; i < MFRAG; ++i)
#pragma unroll
        for (int j = 0; j < NFRAG; ++j) acc[i][j] = make_float4(0.f, 0.f, 0.f, 0.f);

    const int arow = t >> 1;
    const int acb  = (t & 1) * 8;
    int agr = m0 + arow; if (agr >= M) agr = M - 1;
    const float* Ap = A + (size_t)agr * 128 + acb;

    const int brow = t >> 4;
    const int bcb  = (t & 15) * (NT / 16);
    const float* Bp = B + (size_t)brow * NCOLS + n0 + bcb;

    for (int k0 = 0; k0 < 128; k0 += 16) {
        float4 av0 = *reinterpret_cast<const float4*>(Ap + k0);
        float4 av1 = *reinterpret_cast<const float4*>(Ap + k0 + 4);
        As[arow][acb + 0] = f2tf32(av0.x); As[arow][acb + 1] = f2tf32(av0.y);
        As[arow][acb + 2] = f2tf32(av0.z); As[arow][acb + 3] = f2tf32(av0.w);
        As[arow][acb + 4] = f2tf32(av1.x); As[arow][acb + 5] = f2tf32(av1.y);
        As[arow][acb + 6] = f2tf32(av1.z); As[arow][acb + 7] = f2tf32(av1.w);
#pragma unroll
        for (int j = 0; j < NT / 64; ++j) {
            float4 bv = *reinterpret_cast<const float4*>(Bp + (size_t)k0 * NCOLS + j * 4);
            Bs[brow][bcb + j * 4 + 0] = f2tf32(bv.x);
            Bs[brow][bcb + j * 4 + 1] = f2tf32(bv.y);
            Bs[brow][bcb + j * 4 + 2] = f2tf32(bv.z);
            Bs[brow][bcb + j * 4 + 3] = f2tf32(bv.w);
        }
        __syncthreads();

#pragma unroll
        for (int ks = 0; ks < 16; ks += 8) {
            uint32_t afr[MFRAG][4];
#pragma unroll
            for (int fm = 0; fm < MFRAG; ++fm) {
                int mr = warp_m * (MFRAG * 16) + fm * 16 + lr;
                afr[fm][0] = As[mr][ks + lc];
                afr[fm][1] = As[mr + 8][ks + lc];
                afr[fm][2] = As[mr][ks + lc + 4];
                afr[fm][3] = As[mr + 8][ks + lc + 4];
            }
            uint32_t bfr[NFRAG][2];
#pragma unroll
            for (int fn = 0; fn < NFRAG; ++fn) {
                int nc = warp_n * (NFRAG * 8) + fn * 8 + lr;
                bfr[fn][0] = Bs[ks + lc][nc];
                bfr[fn][1] = Bs[ks + lc + 4][nc];
            }
#pragma unroll
            for (int fm = 0; fm < MFRAG; ++fm)
#pragma unroll
                for (int fn = 0; fn < NFRAG; ++fn)
                    mma_tf32(acc[fm][fn], afr[fm], bfr[fn]);
        }
        __syncthreads();
    }

    // ---------------- epilogues ----------------
    if (EPI == 0) {
        const int plane = n0 >> 7;
#pragma unroll
        for (int fm = 0; fm < MFRAG; ++fm) {
            int r0 = m0 + warp_m * (MFRAG * 16) + fm * 16 + lr;
            int r1 = r0 + 8;
#pragma unroll
            for (int fn = 0; fn < NFRAG; ++fn) {
                int cl = warp_n * (NFRAG * 8) + fn * 8 + 2 * lc;
                float4 c = acc[fm][fn];
                if (plane == 0) {
                    if (r0 < M) *reinterpret_cast<float2*>(C + (size_t)r0 * 128 + cl) = make_float2(c.x, c.y);
                    if (r1 < M) *reinterpret_cast<float2*>(C + (size_t)r1 * 128 + cl) = make_float2(c.z, c.w);
                } else {
                    __half* hp = Hkv + (size_t)(plane - 1) * M * 128;
                    if (r0 < M) *reinterpret_cast<__half2*>(hp + (size_t)r0 * 128 + cl) = __floats2half2_rn(c.x, c.y);
                    if (r1 < M) *reinterpret_cast<__half2*>(hp + (size_t)r1 * 128 + cl) = __floats2half2_rn(c.z, c.w);
                }
            }
        }
    } else if (EPI == 2) {
#pragma unroll
        for (int fm = 0; fm < MFRAG; ++fm) {
            int r0 = m0 + warp_m * (MFRAG * 16) + fm * 16 + lr;
            int r1 = r0 + 8;
#pragma unroll
            for (int fn = 0; fn < NFRAG; ++fn) {
                int col = n0 + warp_n * (NFRAG * 8) + fn * 8 + 2 * lc;
                float b0 = bias[col], b1 = bias[col + 1];
                float4 c = acc[fm][fn];
                if (r0 < M)
                    *reinterpret_cast<float2*>(C + (size_t)r0 * NCOLS + col) =
                        make_float2(fmaxf(c.x + b0, 0.f), fmaxf(c.y + b1, 0.f));
                if (r1 < M)
                    *reinterpret_cast<float2*>(C + (size_t)r1 * NCOLS + col) =
                        make_float2(fmaxf(c.z + b0, 0.f), fmaxf(c.w + b1, 0.f));
            }
        }
    } else {   // EPI == 3: bias + resid + LayerNorm -> hn   (n0 == 0, NT == 128)
        __shared__ float sh_s[128][4];
        __shared__ float sh_q[128][4];
        const int mbase = warp_m * (MFRAG * 16);
#pragma unroll
        for (int fm = 0; fm < MFRAG; ++fm) {
            int r0 = m0 + mbase + fm * 16 + lr;
            int r1 = r0 + 8;
            int rr0 = min(r0, M - 1), rr1 = min(r1, M - 1);
            float s0 = 0.f, q0 = 0.f, s1 = 0.f, q1 = 0.f;
#pragma unroll
            for (int fn = 0; fn < NFRAG; ++fn) {
                int cl = warp_n * (NFRAG * 8) + fn * 8 + 2 * lc;
                float2 rA = *reinterpret_cast<const float2*>(resid + (size_t)rr0 * 128 + cl);
                float2 rB = *reinterpret_cast<const float2*>(resid + (size_t)rr1 * 128 + cl);
                float b0 = bias[cl], b1 = bias[cl + 1];
                float4 c = acc[fm][fn];
                c.x += b0 + rA.x; c.y += b1 + rA.y;
                c.z += b0 + rB.x; c.w += b1 + rB.y;
                acc[fm][fn] = c;
                s0 += c.x + c.y; q0 += c.x * c.x + c.y * c.y;
                s1 += c.z + c.w; q1 += c.z * c.z + c.w * c.w;
            }
            // reduce over the 4 lc lanes (same row)
            s0 += __shfl_xor_sync(0xffffffffu, s0, 1); s0 += __shfl_xor_sync(0xffffffffu, s0, 2);
            q0 += __shfl_xor_sync(0xffffffffu, q0, 1); q0 += __shfl_xor_sync(0xffffffffu, q0, 2);
            s1 += __shfl_xor_sync(0xffffffffu, s1, 1); s1 += __shfl_xor_sync(0xffffffffu, s1, 2);
            q1 += __shfl_xor_sync(0xffffffffu, q1, 1); q1 += __shfl_xor_sync(0xffffffffu, q1, 2);
            if (lc == 0) {
                sh_s[mbase + fm * 16 + lr][warp_n] = s0;
                sh_q[mbase + fm * 16 + lr][warp_n] = q0;
                sh_s[mbase + fm * 16 + lr + 8][warp_n] = s1;
                sh_q[mbase + fm * 16 + lr + 8][warp_n] = q1;
            }
        }
        __syncthreads();
#pragma unroll
        for (int fm = 0; fm < MFRAG; ++fm) {
            int l0 = mbase + fm * 16 + lr;
            int l1 = l0 + 8;
            int r0 = m0 + l0, r1 = m0 + l1;
            float mu0 = (sh_s[l0][0] + sh_s[l0][1] + sh_s[l0][2] + sh_s[l0][3]) * (1.f / 128.f);
            float v0  = (sh_q[l0][0] + sh_q[l0][1] + sh_q[l0][2] + sh_q[l0][3]) * (1.f / 128.f) - mu0 * mu0;
            float rs0 = rsqrtf(v0 + 1e-5f);
            float mu1 = (sh_s[l1][0] + sh_s[l1][1] + sh_s[l1][2] + sh_s[l1][3]) * (1.f / 128.f);
            float v1  = (sh_q[l1][0] + sh_q[l1][1] + sh_q[l1][2] + sh_q[l1][3]) * (1.f / 128.f) - mu1 * mu1;
            float rs1 = rsqrtf(v1 + 1e-5f);
#pragma unroll
            for (int fn = 0; fn < NFRAG; ++fn) {
                int cl = warp_n * (NFRAG * 8) + fn * 8 + 2 * lc;
                float lw0 = lnw[cl], lw1 = lnw[cl + 1];
                float lb0 = lnb[cl], lb1 = lnb[cl + 1];
                float4 c = acc[fm][fn];
                if (r0 < M)
                    *reinterpret_cast<float2*>(C + (size_t)r0 * 128 + cl) =
                        make_float2((c.x - mu0) * rs0 * lw0 + lb0, (c.y - mu0) * rs0 * lw1 + lb1);
                if (r1 < M)
                    *reinterpret_cast<float2*>(C + (size_t)r1 * 128 + cl) =
                        make_float2((c.z - mu1) * rs1 * lw0 + lb0, (c.w - mu1) * rs1 * lw1 + lb1);
            }
        }
    }
}

// ---------------- fused CSR attention: 2 warps per node, EPW=8 each ----------------
__global__ __launch_bounds__(256)
void fused_attn(const float* __restrict__ Wedge, int n)
{
    constexpr int EPW = 8;
    int lane = threadIdx.x & 31;
    int wid  = threadIdx.x >> 5;      // 0..7
    int pair = wid >> 1;              // node slot 0..3
    int half = wid & 1;
    int i = blockIdx.x * 4 + pair;
    bool valid = (i < n);
    int ic = valid ? i : (n - 1);
    int hg = lane >> 2;

    int beg = g_rowptr[ic];
    int end = valid ? g_rowptr[ic + 1] : beg;

    float4 q4 = *reinterpret_cast<const float4*>(g_q + (size_t)ic * 128 + lane * 4);
    q4.x *= 0.25f; q4.y *= 0.25f; q4.z *= 0.25f; q4.w *= 0.25f;
    float w0 = Wedge[hg], w1 = Wedge[8 + hg];

    const __half* kplane = g_kv;
    const __half* vplane = g_kv + (size_t)n * 128;

    float4 accv = {0.f, 0.f, 0.f, 0.f};
    float  accd = 0.f;

    for (int j = beg + half * EPW; j < end; j += 2 * EPW) {
        int   idx[EPW];
        float sb[EPW];
#pragma unroll
        for (int u = 0; u < EPW; ++u) {
            int jj = min(j + u, end - 1);
            idx[u] = __ldg(g_esrc + jj);
            float2 ea2 = g_eea[jj];
            sb[u] = ea2.x * w0 + ea2.y * w1;
        }
        uint2 kraw[EPW];
#pragma unroll
        for (int u = 0; u < EPW; ++u)
            kraw[u] = *reinterpret_cast<const uint2*>(kplane + (size_t)idx[u] * 128 + lane * 4);
        uint2 vraw[EPW];
#pragma unroll
        for (int u = 0; u < EPW; ++u)
            vraw[u] = *reinterpret_cast<const uint2*>(vplane + (size_t)idx[u] * 128 + lane * 4);

        float ex[EPW];
#pragma unroll
        for (int u = 0; u < EPW; ++u) {
            float2 ka = __half22float2(*reinterpret_cast<const __half2*>(&kraw[u].x));
            float2 kb = __half22float2(*reinterpret_cast<const __half2*>(&kraw[u].y));
            float p = q4.x * ka.x + q4.y * ka.y + q4.z * kb.x + q4.w * kb.y;
            p += __shfl_xor_sync(0xffffffffu, p, 1);
            p += __shfl_xor_sync(0xffffffffu, p, 2);
            float e = __expf(p + sb[u]);
            ex[u] = (j + u < end) ? e : 0.f;
            accd += ex[u];
        }
#pragma unroll
        for (int u = 0; u < EPW; ++u) {
            float2 va = __half22float2(*reinterpret_cast<const __half2*>(&vraw[u].x));
            float2 vb = __half22float2(*reinterpret_cast<const __half2*>(&vraw[u].y));
            accv.x += ex[u] * va.x;
            accv.y += ex[u] * va.y;
            accv.z += ex[u] * vb.x;
            accv.w += ex[u] * vb.y;
        }
    }

    __shared__ float sv[4][32][5];
    if (half == 1) {
        sv[pair][lane][0] = accv.x;
        sv[pair][lane][1] = accv.y;
        sv[pair][lane][2] = accv.z;
        sv[pair][lane][3] = accv.w;
        sv[pair][lane][4] = accd;
    }
    __syncthreads();
    if (half == 0 && valid) {
        accv.x += sv[pair][lane][0];
        accv.y += sv[pair][lane][1];
        accv.z += sv[pair][lane][2];
        accv.w += sv[pair][lane][3];
        accd   += sv[pair][lane][4];
        float invd = __fdividef(1.f, accd + 1e-16f);
        float4 o = {accv.x * invd, accv.y * invd, accv.z * invd, accv.w * invd};
        *reinterpret_cast<float4*>(g_agg + (size_t)i * 128 + lane * 4) = o;
    }
}

// ---------------- final: out[N,3] = t2[N,64] @ Wc2[64,3] + bc2 ----------------
__global__ __launch_bounds__(256)
void final_kernel(const float* __restrict__ Wc2, const float* __restrict__ bc2,
                  float* __restrict__ out, int n)
{
    int node = (blockIdx.x * blockDim.x + threadIdx.x) >> 5;
    int lane = threadIdx.x & 31;
    if (node >= n) return;

    float2 tv = *reinterpret_cast<const float2*>(g_t2 + (size_t)node * 64 + lane * 2);
    int k0 = lane * 2;
    float s0 = tv.x * Wc2[k0 * 3 + 0] + tv.y * Wc2[k0 * 3 + 3];
    float s1 = tv.x * Wc2[k0 * 3 + 1] + tv.y * Wc2[k0 * 3 + 4];
    float s2 = tv.x * Wc2[k0 * 3 + 2] + tv.y * Wc2[k0 * 3 + 5];
#pragma unroll
    for (int o = 16; o; o >>= 1) {
        s0 += __shfl_xor_sync(0xffffffffu, s0, o);
        s1 += __shfl_xor_sync(0xffffffffu, s1, o);
        s2 += __shfl_xor_sync(0xffffffffu, s2, o);
    }
    if (lane == 0) {
        out[(size_t)node * 3 + 0] = s0 + bc2[0];
        out[(size_t)node * 3 + 1] = s1 + bc2[1];
        out[(size_t)node * 3 + 2] = s2 + bc2[2];
    }
}

// ---------------- launch ----------------
extern "C" void kernel_launch(void* const* d_in, const int* in_sizes, int n_in,
                              void* d_out, int out_size)
{
    const float* x     = (const float*)d_in[0];
    const int*   ei    = (const int*)d_in[1];
    const float* ea    = (const float*)d_in[2];
    const float* Wqkv  = (const float*)d_in[3];
    const float* Wedge = (const float*)d_in[4];
    const float* Wout  = (const float*)d_in[5];
    const float* bout  = (const float*)d_in[6];
    const float* lnw   = (const float*)d_in[7];
    const float* lnb   = (const float*)d_in[8];
    const float* Wc1   = (const float*)d_in[9];
    const float* bc1   = (const float*)d_in[10];
    const float* Wc2   = (const float*)d_in[11];
    const float* bc2   = (const float*)d_in[12];
    float* out = (float*)d_out;

    const int n = in_sizes[0] / 128;
    const int E = in_sizes[1] / 2;

    float *q, *agg, *hn, *t2;
    __half* kv;
    cudaGetSymbolAddress((void**)&q,   g_q);
    cudaGetSymbolAddress((void**)&kv,  g_kv);
    cudaGetSymbolAddress((void**)&agg, g_agg);
    cudaGetSymbolAddress((void**)&hn,  g_hn);
    cudaGetSymbolAddress((void**)&t2,  g_t2);

    // CSR build
    zero_deg<<<(n + 255) / 256, 256>>>(n);
    hist_kernel<<<(E + 255) / 256, 256>>>(ei, E, n);
    scan_kernel<<<1, 1024>>>(n);
    scatter_kernel<<<(E + 255) / 256, 256>>>(ei, ea, E, n);

    // qkv = x @ Wqkv -> q fp32 + k/v fp16 planes
    gemm_tf32<128, 0><<<dim3((n + 127) / 128, 3), 256>>>(
        x, Wqkv, nullptr, nullptr, nullptr, nullptr, q, kv, n, 384);

    // fused per-node attention (2 warps/node)
    fused_attn<<<(n + 3) / 4, 256>>>(Wedge, n);

    // hn = LayerNorm(agg @ Wout + bout + x)   — LN fused in epilogue
    gemm_tf32<128, 3><<<dim3((n + 127) / 128, 1), 256>>>(
        agg, Wout, bout, x, lnw, lnb, hn, nullptr, n, 128);

    // t2 = relu(hn @ Wc1 + bc1)
    gemm_tf32<64, 2><<<dim3((n + 127) / 128, 1), 256>>>(
        hn, Wc1, bc1, nullptr, nullptr, nullptr, t2, nullptr, n, 64);

    // out = t2 @ Wc2 + bc2
    final_kernel<<<(n + 7) / 8, 256>>>(Wc2, bc2, out, n);
}

// round 9
// speedup vs baseline: 1.1007x; 1.0791x over previous
#include <cuda_runtime.h>
#include <cuda_fp16.h>
#include <stdint.h>

#define NMAX 100000
#define EMAX 1600000

// ---------------- scratch (static device globals) ----------------
__device__ __align__(16) float  g_q  [(size_t)NMAX * 128];
// interleaved kv: per node 256 halves = [k0..3 | v0..3 | k4..7 | v4..7 | ...]
// col c: k at half-index 8*(c>>2)+(c&3), v at 8*(c>>2)+4+(c&3)
__device__ __align__(16) __half g_kv [(size_t)NMAX * 256];
__device__ __align__(16) float  g_agg[(size_t)NMAX * 128];
__device__ __align__(16) float  g_h  [(size_t)NMAX * 128];
__device__ __align__(16) float  g_hn [(size_t)NMAX * 128];
__device__ __align__(16) float  g_t2 [(size_t)NMAX * 64];
// CSR
__device__ int    g_deg[NMAX];
__device__ int    g_rowptr[NMAX + 1];
__device__ int    g_cursor[NMAX];
__device__ int    g_esrc[EMAX];
__device__ __align__(8) float2 g_eea[EMAX];

__device__ __forceinline__ int clampi(int v, int hi) {
    return v < 0 ? 0 : (v >= hi ? hi - 1 : v);
}
__device__ __forceinline__ uint32_t f2tf32(float f) {
    uint32_t u;
    asm("cvt.rna.tf32.f32 %0, %1;" : "=r"(u) : "f"(f));
    return u;
}
__device__ __forceinline__ void mma_tf32(float4& c, const uint32_t a[4], const uint32_t b[2]) {
    asm("mma.sync.aligned.m16n8k8.row.col.f32.tf32.tf32.f32 "
        "{%0,%1,%2,%3}, {%4,%5,%6,%7}, {%8,%9}, {%0,%1,%2,%3};"
        : "+f"(c.x), "+f"(c.y), "+f"(c.z), "+f"(c.w)
        : "r"(a[0]), "r"(a[1]), "r"(a[2]), "r"(a[3]), "r"(b[0]), "r"(b[1]));
}

// ---------------- CSR build ----------------
__global__ void zero_deg(int n) {
    int i = blockIdx.x * blockDim.x + threadIdx.x;
    if (i < n) g_deg[i] = 0;
}
__global__ void hist_kernel(const int* __restrict__ ei, int E, int n) {
    int e = blockIdx.x * blockDim.x + threadIdx.x;
    if (e < E) atomicAdd(&g_deg[clampi(ei[E + e], n)], 1);
}
__global__ __launch_bounds__(1024)
void scan_kernel(int n) {
    __shared__ int sh[1024];
    int t = threadIdx.x;
    int chunk = (n + 1023) >> 10;
    int b = t * chunk;
    int e = min(n, b + chunk);
    int s = 0;
    for (int i = b; i < e; ++i) s += g_deg[i];
    sh[t] = s;
    __syncthreads();
    for (int off = 1; off < 1024; off <<= 1) {
        int v = (t >= off) ? sh[t - off] : 0;
        __syncthreads();
        sh[t] += v;
        __syncthreads();
    }
    int base = (t == 0) ? 0 : sh[t - 1];
    for (int i = b; i < e; ++i) {
        int d = g_deg[i];
        g_rowptr[i] = base;
        g_cursor[i] = base;
        base += d;
    }
    if (t == 1023) g_rowptr[n] = sh[1023];
}
__global__ void scatter_kernel(const int* __restrict__ ei, const float* __restrict__ ea,
                               int E, int n) {
    int e = blockIdx.x * blockDim.x + threadIdx.x;
    if (e >= E) return;
    int src = clampi(ei[e], n);
    int dst = clampi(ei[E + e], n);
    int pos = atomicAdd(&g_cursor[dst], 1);
    g_esrc[pos] = src;
    g_eea[pos]  = *reinterpret_cast<const float2*>(ea + (size_t)e * 2);
}

// ---------------- tf32 tensor-core GEMM, K=128, M-tile=128, N-tile=NT ----------------
// EPI 0: qkv split -> q fp32 plane + interleaved kv fp16
// EPI 1: bias + resid -> C (NCOLS=128)
// EPI 2: bias + relu  -> C (NCOLS=64, NT=64)
template<int NT, int EPI>
__global__ __launch_bounds__(256)
void gemm_tf32(const float* __restrict__ A, const float* __restrict__ B,
               const float* __restrict__ bias, const float* __restrict__ resid,
               float* __restrict__ C, __half* __restrict__ Hkv, int M, int NCOLS)
{
    constexpr int WM = (NT == 128) ? 2 : 4;
    constexpr int WN = 8 / WM;
    constexpr int MFRAG = 8 / WM;
    constexpr int NFRAG = NT / (WN * 8);

    __shared__ uint32_t As[128][20];
    __shared__ uint32_t Bs[16][NT + 8];

    const int t = threadIdx.x;
    const int lane = t & 31;
    const int wid  = t >> 5;
    const int warp_m = wid / WN;
    const int warp_n = wid % WN;
    const int m0 = blockIdx.x * 128;
    const int n0 = blockIdx.y * NT;
    const int lr = lane >> 2, lc = lane & 3;

    float4 acc[MFRAG][NFRAG];
#pragma unroll
    for (int i = 0; i < MFRAG; ++i)
#pragma unroll
        for (int j = 0; j < NFRAG; ++j) acc[i][j] = make_float4(0.f, 0.f, 0.f, 0.f);

    const int arow = t >> 1;
    const int acb  = (t & 1) * 8;
    int agr = m0 + arow; if (agr >= M) agr = M - 1;
    const float* Ap = A + (size_t)agr * 128 + acb;

    const int brow = t >> 4;
    const int bcb  = (t & 15) * (NT / 16);
    const float* Bp = B + (size_t)brow * NCOLS + n0 + bcb;

    for (int k0 = 0; k0 < 128; k0 += 16) {
        float4 av0 = *reinterpret_cast<const float4*>(Ap + k0);
        float4 av1 = *reinterpret_cast<const float4*>(Ap + k0 + 4);
        As[arow][acb + 0] = f2tf32(av0.x); As[arow][acb + 1] = f2tf32(av0.y);
        As[arow][acb + 2] = f2tf32(av0.z); As[arow][acb + 3] = f2tf32(av0.w);
        As[arow][acb + 4] = f2tf32(av1.x); As[arow][acb + 5] = f2tf32(av1.y);
        As[arow][acb + 6] = f2tf32(av1.z); As[arow][acb + 7] = f2tf32(av1.w);
#pragma unroll
        for (int j = 0; j < NT / 64; ++j) {
            float4 bv = *reinterpret_cast<const float4*>(Bp + (size_t)k0 * NCOLS + j * 4);
            Bs[brow][bcb + j * 4 + 0] = f2tf32(bv.x);
            Bs[brow][bcb + j * 4 + 1] = f2tf32(bv.y);
            Bs[brow][bcb + j * 4 + 2] = f2tf32(bv.z);
            Bs[brow][bcb + j * 4 + 3] = f2tf32(bv.w);
        }
        __syncthreads();

#pragma unroll
        for (int ks = 0; ks < 16; ks += 8) {
            uint32_t afr[MFRAG][4];
#pragma unroll
            for (int fm = 0; fm < MFRAG; ++fm) {
                int mr = warp_m * (MFRAG * 16) + fm * 16 + lr;
                afr[fm][0] = As[mr][ks + lc];
                afr[fm][1] = As[mr + 8][ks + lc];
                afr[fm][2] = As[mr][ks + lc + 4];
                afr[fm][3] = As[mr + 8][ks + lc + 4];
            }
            uint32_t bfr[NFRAG][2];
#pragma unroll
            for (int fn = 0; fn < NFRAG; ++fn) {
                int nc = warp_n * (NFRAG * 8) + fn * 8 + lr;
                bfr[fn][0] = Bs[ks + lc][nc];
                bfr[fn][1] = Bs[ks + lc + 4][nc];
            }
#pragma unroll
            for (int fm = 0; fm < MFRAG; ++fm)
#pragma unroll
                for (int fn = 0; fn < NFRAG; ++fn)
                    mma_tf32(acc[fm][fn], afr[fm], bfr[fn]);
        }
        __syncthreads();
    }

    const int plane = n0 >> 7;
#pragma unroll
    for (int fm = 0; fm < MFRAG; ++fm) {
        int r0 = m0 + warp_m * (MFRAG * 16) + fm * 16 + lr;
        int r1 = r0 + 8;
#pragma unroll
        for (int fn = 0; fn < NFRAG; ++fn) {
            int cl = warp_n * (NFRAG * 8) + fn * 8 + 2 * lc;
            float4 c = acc[fm][fn];
            if (EPI == 0) {
                if (plane == 0) {
                    if (r0 < M) *reinterpret_cast<float2*>(C + (size_t)r0 * 128 + cl) = make_float2(c.x, c.y);
                    if (r1 < M) *reinterpret_cast<float2*>(C + (size_t)r1 * 128 + cl) = make_float2(c.z, c.w);
                } else {
                    // interleaved kv: col cl -> half-index 8*(cl>>2)+(cl&3), +4 for v plane
                    int hi = ((cl >> 2) << 3) + (cl & 3) + ((plane == 2) ? 4 : 0);
                    if (r0 < M) *reinterpret_cast<__half2*>(Hkv + (size_t)r0 * 256 + hi) = __floats2half2_rn(c.x, c.y);
                    if (r1 < M) *reinterpret_cast<__half2*>(Hkv + (size_t)r1 * 256 + hi) = __floats2half2_rn(c.z, c.w);
                }
            } else {
                int col = n0 + cl;
                float b0 = bias[col], b1 = bias[col + 1];
                if (EPI == 1) {
                    if (r0 < M) {
                        float2 rr = *reinterpret_cast<const float2*>(resid + (size_t)r0 * NCOLS + col);
                        *reinterpret_cast<float2*>(C + (size_t)r0 * NCOLS + col) =
                            make_float2(c.x + b0 + rr.x, c.y + b1 + rr.y);
                    }
                    if (r1 < M) {
                        float2 rr = *reinterpret_cast<const float2*>(resid + (size_t)r1 * NCOLS + col);
                        *reinterpret_cast<float2*>(C + (size_t)r1 * NCOLS + col) =
                            make_float2(c.z + b0 + rr.x, c.w + b1 + rr.y);
                    }
                } else {
                    if (r0 < M)
                        *reinterpret_cast<float2*>(C + (size_t)r0 * NCOLS + col) =
                            make_float2(fmaxf(c.x + b0, 0.f), fmaxf(c.y + b1, 0.f));
                    if (r1 < M)
                        *reinterpret_cast<float2*>(C + (size_t)r1 * NCOLS + col) =
                            make_float2(fmaxf(c.z + b0, 0.f), fmaxf(c.w + b1, 0.f));
                }
            }
        }
    }
}

// ---------------- fused CSR attention: 1 warp/node, EPW=8, ONE LDG.128 per edge ----------------
__global__ __launch_bounds__(128)
void fused_attn(const float* __restrict__ Wedge, int n)
{
    constexpr int EPW = 8;
    int i    = (blockIdx.x * blockDim.x + threadIdx.x) >> 5;
    int lane = threadIdx.x & 31;
    if (i >= n) return;
    int hg = lane >> 2;

    int beg = g_rowptr[i];
    int end = g_rowptr[i + 1];

    float4 q4 = *reinterpret_cast<const float4*>(g_q + (size_t)i * 128 + lane * 4);
    q4.x *= 0.25f; q4.y *= 0.25f; q4.z *= 0.25f; q4.w *= 0.25f;
    float w0 = Wedge[hg], w1 = Wedge[8 + hg];

    float4 accv = {0.f, 0.f, 0.f, 0.f};
    float  accd = 0.f;

    for (int j = beg; j < end; j += EPW) {
        int   idx[EPW];
        float sb[EPW];
#pragma unroll
        for (int u = 0; u < EPW; ++u) {
            int jj = min(j + u, end - 1);
            idx[u] = __ldg(g_esrc + jj);
            float2 ea2 = g_eea[jj];
            sb[u] = ea2.x * w0 + ea2.y * w1;
        }
        // ONE fully-coalesced 16B load per edge per lane (k 8B + v 8B interleaved)
        uint4 kv[EPW];
#pragma unroll
        for (int u = 0; u < EPW; ++u)
            kv[u] = *reinterpret_cast<const uint4*>(g_kv + (size_t)idx[u] * 256 + lane * 8);

        float ex[EPW];
#pragma unroll
        for (int u = 0; u < EPW; ++u) {
            float2 ka = __half22float2(*reinterpret_cast<const __half2*>(&kv[u].x));
            float2 kb = __half22float2(*reinterpret_cast<const __half2*>(&kv[u].y));
            float p = q4.x * ka.x + q4.y * ka.y + q4.z * kb.x + q4.w * kb.y;
            p += __shfl_xor_sync(0xffffffffu, p, 1);
            p += __shfl_xor_sync(0xffffffffu, p, 2);
            float e = __expf(p + sb[u]);
            ex[u] = (j + u < end) ? e : 0.f;
            accd += ex[u];
        }
#pragma unroll
        for (int u = 0; u < EPW; ++u) {
            float2 va = __half22float2(*reinterpret_cast<const __half2*>(&kv[u].z));
            float2 vb = __half22float2(*reinterpret_cast<const __half2*>(&kv[u].w));
            accv.x += ex[u] * va.x;
            accv.y += ex[u] * va.y;
            accv.z += ex[u] * vb.x;
            accv.w += ex[u] * vb.y;
        }
    }

    float invd = __fdividef(1.f, accd + 1e-16f);
    float4 o = {accv.x * invd, accv.y * invd, accv.z * invd, accv.w * invd};
    *reinterpret_cast<float4*>(g_agg + (size_t)i * 128 + lane * 4) = o;
}

// ---------------- layernorm ----------------
__global__ __launch_bounds__(256)
void ln_kernel(const float* __restrict__ lw, const float* __restrict__ lb, int n)
{
    int node = (blockIdx.x * blockDim.x + threadIdx.x) >> 5;
    int lane = threadIdx.x & 31;
    if (node >= n) return;

    float4 v = *reinterpret_cast<const float4*>(g_h + (size_t)node * 128 + lane * 4);
    float s = v.x + v.y + v.z + v.w;
    float q = v.x * v.x + v.y * v.y + v.z * v.z + v.w * v.w;
#pragma unroll
    for (int o = 16; o; o >>= 1) {
        s += __shfl_xor_sync(0xffffffffu, s, o);
        q += __shfl_xor_sync(0xffffffffu, q, o);
    }
    float mu  = s * (1.f / 128.f);
    float var = q * (1.f / 128.f) - mu * mu;
    float rs  = rsqrtf(var + 1e-5f);
    float4 w4 = *reinterpret_cast<const float4*>(lw + lane * 4);
    float4 b4 = *reinterpret_cast<const float4*>(lb + lane * 4);
    float4 o;
    o.x = (v.x - mu) * rs * w4.x + b4.x;
    o.y = (v.y - mu) * rs * w4.y + b4.y;
    o.z = (v.z - mu) * rs * w4.z + b4.z;
    o.w = (v.w - mu) * rs * w4.w + b4.w;
    *reinterpret_cast<float4*>(g_hn + (size_t)node * 128 + lane * 4) = o;
}

// ---------------- final: out[N,3] = t2[N,64] @ Wc2[64,3] + bc2 ----------------
__global__ __launch_bounds__(256)
void final_kernel(const float* __restrict__ Wc2, const float* __restrict__ bc2,
                  float* __restrict__ out, int n)
{
    int node = (blockIdx.x * blockDim.x + threadIdx.x) >> 5;
    int lane = threadIdx.x & 31;
    if (node >= n) return;

    float2 tv = *reinterpret_cast<const float2*>(g_t2 + (size_t)node * 64 + lane * 2);
    int k0 = lane * 2;
    float s0 = tv.x * Wc2[k0 * 3 + 0] + tv.y * Wc2[k0 * 3 + 3];
    float s1 = tv.x * Wc2[k0 * 3 + 1] + tv.y * Wc2[k0 * 3 + 4];
    float s2 = tv.x * Wc2[k0 * 3 + 2] + tv.y * Wc2[k0 * 3 + 5];
#pragma unroll
    for (int o = 16; o; o >>= 1) {
        s0 += __shfl_xor_sync(0xffffffffu, s0, o);
        s1 += __shfl_xor_sync(0xffffffffu, s1, o);
        s2 += __shfl_xor_sync(0xffffffffu, s2, o);
    }
    if (lane == 0) {
        out[(size_t)node * 3 + 0] = s0 + bc2[0];
        out[(size_t)node * 3 + 1] = s1 + bc2[1];
        out[(size_t)node * 3 + 2] = s2 + bc2[2];
    }
}

// ---------------- launch ----------------
extern "C" void kernel_launch(void* const* d_in, const int* in_sizes, int n_in,
                              void* d_out, int out_size)
{
    const float* x     = (const float*)d_in[0];
    const int*   ei    = (const int*)d_in[1];
    const float* ea    = (const float*)d_in[2];
    const float* Wqkv  = (const float*)d_in[3];
    const float* Wedge = (const float*)d_in[4];
    const float* Wout  = (const float*)d_in[5];
    const float* bout  = (const float*)d_in[6];
    const float* lnw   = (const float*)d_in[7];
    const float* lnb   = (const float*)d_in[8];
    const float* Wc1   = (const float*)d_in[9];
    const float* bc1   = (const float*)d_in[10];
    const float* Wc2   = (const float*)d_in[11];
    const float* bc2   = (const float*)d_in[12];
    float* out = (float*)d_out;

    const int n = in_sizes[0] / 128;
    const int E = in_sizes[1] / 2;

    float *q, *agg, *h, *hn, *t2;
    __half* kv;
    cudaGetSymbolAddress((void**)&q,   g_q);
    cudaGetSymbolAddress((void**)&kv,  g_kv);
    cudaGetSymbolAddress((void**)&agg, g_agg);
    cudaGetSymbolAddress((void**)&h,   g_h);
    cudaGetSymbolAddress((void**)&hn,  g_hn);
    cudaGetSymbolAddress((void**)&t2,  g_t2);

    // CSR build
    zero_deg<<<(n + 255) / 256, 256>>>(n);
    hist_kernel<<<(E + 255) / 256, 256>>>(ei, E, n);
    scan_kernel<<<1, 1024>>>(n);
    scatter_kernel<<<(E + 255) / 256, 256>>>(ei, ea, E, n);

    // qkv = x @ Wqkv -> q fp32 plane + interleaved kv fp16
    gemm_tf32<128, 0><<<dim3((n + 127) / 128, 3), 256>>>(
        x, Wqkv, nullptr, nullptr, q, kv, n, 384);

    // fused per-node attention
    fused_attn<<<(n + 3) / 4, 128>>>(Wedge, n);

    // h = agg @ Wout + bout + x
    gemm_tf32<128, 1><<<dim3((n + 127) / 128, 1), 256>>>(
        agg, Wout, bout, x, h, nullptr, n, 128);

    // layernorm
    ln_kernel<<<(n + 7) / 8, 256>>>(lnw, lnb, n);

    // t2 = relu(hn @ Wc1 + bc1)
    gemm_tf32<64, 2><<<dim3((n + 127) / 128, 1), 256>>>(
        hn, Wc1, bc1, nullptr, t2, nullptr, n, 64);

    // out = t2 @ Wc2 + bc2
    final_kernel<<<(n + 7) / 8, 256>>>(Wc2, bc2, out, n);
}